// round 4
// baseline (speedup 1.0000x reference)
#include <cuda_runtime.h>
#include <cstdint>
#include <cstddef>

#define BB 512
#define TT 512
#define LBL 126
#define NS 128            // L + 2
#define FILLF (-1000.0f)
#define LOG2E 1.4426950408889634f
#define LN2   0.6931471805599453f
#define NB 2              // batches per CTA
#define NTHR (NB * 128)

__device__ float g_t2[NS * NS];
__device__ float g_total[BB];
__device__ float g_real[BB];

__device__ __forceinline__ float ex2f(float x) {
    float y; asm("ex2.approx.ftz.f32 %0, %1;" : "=f"(y) : "f"(x)); return y;
}
__device__ __forceinline__ float lg2f(float x) {
    float y; asm("lg2.approx.ftz.f32 %0, %1;" : "=f"(y) : "f"(x)); return y;
}

// Pre-scale transitions into log2 domain.
__global__ void prep_kernel(const float* __restrict__ trans) {
    int i = blockIdx.x * blockDim.x + threadIdx.x;
    if (i < NS * NS) g_t2[i] = trans[i] * LOG2E;
}

// Main forward scan. One 128-thread group per batch, NB groups per CTA.
// Thread j owns column j. Everything in log2 domain (q = pre * log2e).
__global__ void __launch_bounds__(NTHR, 2) main_kernel(const float* __restrict__ emis) {
    extern __shared__ float sm[];
    float* t2s  = sm;                 // NS*NS scaled transitions
    float* q    = sm + NS * NS;       // NB * NS running scores
    float* red  = q + NB * NS;        // NB * 4 warp partials
    float* red2 = red + NB * 4;       // NB * 4 warp partials (final)

    const int tid  = threadIdx.x;
    const int g    = tid >> 7;        // batch group within CTA
    const int j    = tid & 127;       // column index
    const int w    = (tid >> 5) & 3;  // warp within group
    const int lane = tid & 31;
    const int b    = blockIdx.x * NB + g;

    for (int k = tid; k < NS * NS; k += NTHR) t2s[k] = g_t2[k];

    float* qg = q + g * NS;
    // E[0]: FILL everywhere except column L (start) = 0.
    qg[j] = (j == LBL) ? 0.0f : FILLF * LOG2E;
    __syncthreads();

    const float* erow = emis + (size_t)b * TT * LBL;

    for (int t = 0; t <= TT; ++t) {
        // obs row for this step (E[t+1]), scaled to log2 domain.
        float obs2;
        if (t < TT) {
            obs2 = (j < LBL) ? erow[(size_t)t * LBL + j] * LOG2E : FILLF * LOG2E;
        } else {
            obs2 = (j == LBL + 1) ? 0.0f : FILLF * LOG2E;
        }

        // Pass 1: mk_j = max_i (q_i + t2_ij). 4 accumulators to break the max chain.
        float m0 = -1e30f, m1 = -1e30f, m2 = -1e30f, m3 = -1e30f;
        #pragma unroll 8
        for (int i = 0; i < NS; i += 4) {
            float4 q4 = *reinterpret_cast<const float4*>(qg + i);  // broadcast
            m0 = fmaxf(m0, q4.x + t2s[(i + 0) * NS + j]);
            m1 = fmaxf(m1, q4.y + t2s[(i + 1) * NS + j]);
            m2 = fmaxf(m2, q4.z + t2s[(i + 2) * NS + j]);
            m3 = fmaxf(m3, q4.w + t2s[(i + 3) * NS + j]);
        }
        const float mk = fmaxf(fmaxf(m0, m1), fmaxf(m2, m3));

        // Pass 2: s_j = sum_i 2^(q_i + t2_ij - mk_j). Exponent always <= 0.
        float s0 = 0.f, s1 = 0.f, s2 = 0.f, s3 = 0.f;
        #pragma unroll 8
        for (int i = 0; i < NS; i += 4) {
            float4 q4 = *reinterpret_cast<const float4*>(qg + i);
            s0 += ex2f(q4.x + t2s[(i + 0) * NS + j] - mk);
            s1 += ex2f(q4.y + t2s[(i + 1) * NS + j] - mk);
            s2 += ex2f(q4.z + t2s[(i + 2) * NS + j] - mk);
            s3 += ex2f(q4.w + t2s[(i + 3) * NS + j] - mk);
        }
        float s = (s0 + s1) + (s2 + s3);

        // Whole-matrix sum S over the group's 128 threads (fixed order -> deterministic).
        #pragma unroll
        for (int o = 16; o > 0; o >>= 1) s += __shfl_xor_sync(0xffffffffu, s, o);
        if (lane == 0) red[g * 4 + w] = s;
        __syncthreads();   // also guarantees all q reads of this step are done
        const float S = (red[g * 4 + 0] + red[g * 4 + 1]) + (red[g * 4 + 2] + red[g * 4 + 3]);

        qg[j] = obs2 + mk + lg2f(S);
        __syncthreads();
    }

    // Final per-batch logsumexp over q.
    const float v = qg[j];
    float m = v;
    #pragma unroll
    for (int o = 16; o > 0; o >>= 1) m = fmaxf(m, __shfl_xor_sync(0xffffffffu, m, o));
    if (lane == 0) red[g * 4 + w] = m;
    __syncthreads();
    m = fmaxf(fmaxf(red[g * 4 + 0], red[g * 4 + 1]), fmaxf(red[g * 4 + 2], red[g * 4 + 3]));

    float e = ex2f(v - m);
    #pragma unroll
    for (int o = 16; o > 0; o >>= 1) e += __shfl_xor_sync(0xffffffffu, e, o);
    if (lane == 0) red2[g * 4 + w] = e;
    __syncthreads();
    if (j == 0) {
        const float S2 = (red2[g * 4 + 0] + red2[g * 4 + 1]) + (red2[g * 4 + 2] + red2[g * 4 + 3]);
        g_total[b] = (m + lg2f(S2)) * LN2;  // back to natural log units
    }
}

// Real path score per batch: emission gather + transition chain.
__global__ void real_kernel(const float* __restrict__ emis,
                            const int* __restrict__ labels,
                            const float* __restrict__ trans) {
    const int b = blockIdx.x;
    const int tid = threadIdx.x;  // 128 threads
    const int*   lab = labels + (size_t)b * TT;
    const float* eb  = emis + (size_t)b * TT * LBL;

    float acc = 0.f;
    for (int t = tid; t < TT; t += 128) {
        const int l = lab[t];
        acc += eb[(size_t)t * LBL + l];
        const int prev = (t == 0) ? LBL : lab[t - 1];
        acc += trans[prev * NS + l];
    }
    if (tid == 0) acc += trans[lab[TT - 1] * NS + (LBL + 1)];  // last -> END

    __shared__ float rr[4];
    #pragma unroll
    for (int o = 16; o > 0; o >>= 1) acc += __shfl_xor_sync(0xffffffffu, acc, o);
    if ((tid & 31) == 0) rr[tid >> 5] = acc;
    __syncthreads();
    if (tid == 0) g_real[b] = (rr[0] + rr[1]) + (rr[2] + rr[3]);
}

// Deterministic final sum over batches.
__global__ void final_kernel(float* __restrict__ out) {
    const int b = threadIdx.x;  // 512 threads
    float v = g_total[b] - g_real[b];
    __shared__ float rr[16];
    #pragma unroll
    for (int o = 16; o > 0; o >>= 1) v += __shfl_xor_sync(0xffffffffu, v, o);
    if ((b & 31) == 0) rr[b >> 5] = v;
    __syncthreads();
    if (b < 16) {
        float x = rr[b];
        #pragma unroll
        for (int o = 8; o > 0; o >>= 1) x += __shfl_xor_sync(0x0000ffffu, x, o);
        if (b == 0) out[0] = x;
    }
}

extern "C" void kernel_launch(void* const* d_in, const int* in_sizes, int n_in,
                              void* d_out, int out_size) {
    const float* emis   = (const float*)d_in[0];
    const int*   labels = (const int*)d_in[1];
    const float* trans  = (const float*)d_in[2];
    float*       out    = (float*)d_out;

    const size_t smem = (NS * NS + NB * NS + NB * 8) * sizeof(float);
    cudaFuncSetAttribute(main_kernel, cudaFuncAttributeMaxDynamicSharedMemorySize, (int)smem);

    prep_kernel<<<(NS * NS + 255) / 256, 256>>>(trans);
    main_kernel<<<BB / NB, NTHR, smem>>>(emis);
    real_kernel<<<BB, 128>>>(emis, labels, trans);
    final_kernel<<<1, BB>>>(out);
}

// round 5
// speedup vs baseline: 2.2349x; 2.2349x over previous
#include <cuda_runtime.h>
#include <cstdint>
#include <cstddef>

#define BB 512
#define TT 512
#define LBL 126
#define NS 128            // L + 2
#define STRIDE 132        // padded row stride for conflict-free LDS.128
#define FILLF (-1000.0f)
#define LOG2E 1.4426950408889634f
#define LN2   0.6931471805599453f
#define NTHR 256          // 2 groups of 128; each thread = 1 column x 2 batches

__device__ float g_V[NS * NS];    // V[j*NS+i] = 2^(trans[i][j]*log2e)  (transposed)
__device__ float g_total[BB];
__device__ float g_real[BB];

__device__ __forceinline__ float ex2f(float x) {
    float y; asm("ex2.approx.ftz.f32 %0, %1;" : "=f"(y) : "f"(x)); return y;
}
__device__ __forceinline__ float lg2f(float x) {
    float y; asm("lg2.approx.ftz.f32 %0, %1;" : "=f"(y) : "f"(x)); return y;
}

// Packed MAC: p = u2*v2 (f32x2), P2 += p (f32x2), m0/m1 = max with p's halves.
__device__ __forceinline__ void mac2(uint64_t u2, uint64_t v2,
                                     uint64_t& P2, float& m0, float& m1) {
    asm("{\n\t"
        ".reg .b64 p;\n\t"
        ".reg .f32 lo, hi;\n\t"
        "mul.rn.f32x2 p, %3, %4;\n\t"
        "mov.b64 {lo, hi}, p;\n\t"
        "add.rn.f32x2 %0, %0, p;\n\t"
        "max.f32 %1, %1, lo;\n\t"
        "max.f32 %2, %2, hi;\n\t"
        "}"
        : "+l"(P2), "+f"(m0), "+f"(m1)
        : "l"(u2), "l"(v2));
}

__device__ __forceinline__ float2 u64f2(uint64_t x) {
    float2 r; asm("mov.b64 {%0,%1}, %2;" : "=f"(r.x), "=f"(r.y) : "l"(x)); return r;
}

// Precompute V (transposed, exponentiated, log2 domain).
__global__ void prep_kernel(const float* __restrict__ trans) {
    int o = blockIdx.x * blockDim.x + threadIdx.x;   // o = j*NS + i
    if (o < NS * NS) {
        int j = o >> 7, i = o & 127;
        g_V[o] = ex2f(trans[i * NS + j] * LOG2E);
    }
}

// Main forward scan. 128 CTAs x 256 threads; group g (128 thr) handles
// batches (bid*4 + 2g, bid*4 + 2g + 1); thread j owns column j of both.
__global__ void __launch_bounds__(NTHR, 1) main_kernel(const float* __restrict__ emis) {
    extern __shared__ float sm[];
    const int tid  = threadIdx.x;
    const int g    = tid >> 7;
    const int j    = tid & 127;
    const int w    = (tid >> 5) & 3;
    const int lane = tid & 31;

    float*  VT   = sm;                                 // NS*STRIDE
    float*  uA   = sm + NS * STRIDE + g * 256;         // 128 per batch
    float*  uB   = uA + 128;
    float4* red1 = reinterpret_cast<float4*>(sm + NS * STRIDE + 512) + g * 4;
    float2* red2 = reinterpret_cast<float2*>(sm + NS * STRIDE + 512 + 32) + g * 4;

    for (int k = tid; k < NS * NS; k += NTHR)
        VT[(k >> 7) * STRIDE + (k & 127)] = g_V[k];

    const int bA = blockIdx.x * 4 + g * 2;
    const int bB = bA + 1;
    const float CF = FILLF * LOG2E;

    uA[j] = (j == LBL) ? 1.0f : 0.0f;   // u0 = 2^(E0_j - max E0)
    uB[j] = (j == LBL) ? 1.0f : 0.0f;
    float UA = 1.0f, UB = 1.0f, accA = 0.0f, accB = 0.0f;

    const float* eA = emis + (size_t)bA * TT * LBL;
    const float* eB = emis + (size_t)bB * TT * LBL;
    float rawA = 0.0f, rawB = 0.0f;
    if (j < LBL) { rawA = eA[j]; rawB = eB[j]; }
    __syncthreads();

    const float* vrow = VT + j * STRIDE;

    for (int t = 0; t <= TT; ++t) {
        float obsA, obsB;
        if (t < TT) {
            obsA = (j < LBL) ? rawA * LOG2E : CF;
            obsB = (j < LBL) ? rawB * LOG2E : CF;
        } else {
            obsA = (j == LBL + 1) ? 0.0f : CF;
            obsB = obsA;
        }
        if (t + 1 < TT && j < LBL) {          // prefetch next emission row
            rawA = eA[(size_t)(t + 1) * LBL + j];
            rawB = eB[(size_t)(t + 1) * LBL + j];
        }

        // Inner matvec+max: p = u_i * V_ij ; mp = max p ; P = sum p.
        uint64_t PA0 = 0, PA1 = 0, PB0 = 0, PB1 = 0;
        float mA0 = 0.f, mA1 = 0.f, mA2 = 0.f, mA3 = 0.f;
        float mB0 = 0.f, mB1 = 0.f, mB2 = 0.f, mB3 = 0.f;
        #pragma unroll 8
        for (int i = 0; i < NS; i += 4) {
            ulonglong2 v2 = *reinterpret_cast<const ulonglong2*>(vrow + i);
            ulonglong2 a2 = *reinterpret_cast<const ulonglong2*>(uA + i);  // broadcast
            ulonglong2 b2 = *reinterpret_cast<const ulonglong2*>(uB + i);  // broadcast
            mac2(a2.x, v2.x, PA0, mA0, mA1);
            mac2(a2.y, v2.y, PA1, mA2, mA3);
            mac2(b2.x, v2.x, PB0, mB0, mB1);
            mac2(b2.y, v2.y, PB1, mB2, mB3);
        }
        float2 fA0 = u64f2(PA0), fA1 = u64f2(PA1);
        float2 fB0 = u64f2(PB0), fB1 = u64f2(PB1);
        const float PsA = (fA0.x + fA0.y) + (fA1.x + fA1.y);
        const float PsB = (fB0.x + fB0.y) + (fB1.x + fB1.y);
        const float mpA = fmaxf(fmaxf(mA0, mA1), fmaxf(mA2, mA3));
        const float mpB = fmaxf(fmaxf(mB0, mB1), fmaxf(mB2, mB3));

        // lm_j = mk_j - qm ; s_j = P/mp (argmax term == 1, like the reference).
        // Column L: all V==0 -> s_L = sum_i u_i = U, lm_L = FILL (constant row).
        const float lmA = (j == LBL) ? CF : lg2f(mpA);
        const float lmB = (j == LBL) ? CF : lg2f(mpB);
        const float sA  = (j == LBL) ? UA : PsA * ex2f(-lmA);
        const float sB  = (j == LBL) ? UB : PsB * ex2f(-lmB);
        const float dA  = obsA + lmA;   // pre_new_j = A + lg2S + d_j
        const float dB  = obsB + lmB;

        // Reduce (sum s, max d) over the 128-thread group. Fixed order.
        float rsA = sA, rsB = sB, rdA = dA, rdB = dB;
        #pragma unroll
        for (int o = 16; o > 0; o >>= 1) {
            rsA += __shfl_xor_sync(0xffffffffu, rsA, o);
            rsB += __shfl_xor_sync(0xffffffffu, rsB, o);
            rdA = fmaxf(rdA, __shfl_xor_sync(0xffffffffu, rdA, o));
            rdB = fmaxf(rdB, __shfl_xor_sync(0xffffffffu, rdB, o));
        }
        if (lane == 0) red1[w] = make_float4(rsA, rsB, rdA, rdB);
        __syncthreads();   // also: everyone is past the u reads of this step
        const float4 q0 = red1[0], q1 = red1[1], q2 = red1[2], q3 = red1[3];
        const float SA  = (q0.x + q1.x) + (q2.x + q3.x);
        const float SB  = (q0.y + q1.y) + (q2.y + q3.y);
        const float dmA = fmaxf(fmaxf(q0.z, q1.z), fmaxf(q2.z, q3.z));
        const float dmB = fmaxf(fmaxf(q0.w, q1.w), fmaxf(q2.w, q3.w));

        // Next-step u, and U = sum u (needed for column L next step + final LSE).
        const float nuA = ex2f(dA - dmA);
        const float nuB = ex2f(dB - dmB);
        uA[j] = nuA;
        uB[j] = nuB;
        float ruA = nuA, ruB = nuB;
        #pragma unroll
        for (int o = 16; o > 0; o >>= 1) {
            ruA += __shfl_xor_sync(0xffffffffu, ruA, o);
            ruB += __shfl_xor_sync(0xffffffffu, ruB, o);
        }
        if (lane == 0) red2[w] = make_float2(ruA, ruB);
        __syncthreads();
        const float2 r0 = red2[0], r1 = red2[1], r2 = red2[2], r3 = red2[3];
        UA = (r0.x + r1.x) + (r2.x + r3.x);
        UB = (r0.y + r1.y) + (r2.y + r3.y);

        accA += dmA + lg2f(SA);   // A_t = A_{t-1} + lg2 S + dm  (== max_j pre_j)
        accB += dmB + lg2f(SB);
    }

    if (j == 0) {
        g_total[bA] = (accA + lg2f(UA)) * LN2;
        g_total[bB] = (accB + lg2f(UB)) * LN2;
    }
}

// Real path score per batch: emission gather + transition chain.
__global__ void real_kernel(const float* __restrict__ emis,
                            const int* __restrict__ labels,
                            const float* __restrict__ trans) {
    const int b = blockIdx.x;
    const int tid = threadIdx.x;  // 128 threads
    const int*   lab = labels + (size_t)b * TT;
    const float* eb  = emis + (size_t)b * TT * LBL;

    float acc = 0.f;
    for (int t = tid; t < TT; t += 128) {
        const int l = lab[t];
        acc += eb[(size_t)t * LBL + l];
        const int prev = (t == 0) ? LBL : lab[t - 1];
        acc += trans[prev * NS + l];
    }
    if (tid == 0) acc += trans[lab[TT - 1] * NS + (LBL + 1)];  // last -> END

    __shared__ float rr[4];
    #pragma unroll
    for (int o = 16; o > 0; o >>= 1) acc += __shfl_xor_sync(0xffffffffu, acc, o);
    if ((tid & 31) == 0) rr[tid >> 5] = acc;
    __syncthreads();
    if (tid == 0) g_real[b] = (rr[0] + rr[1]) + (rr[2] + rr[3]);
}

// Deterministic final sum over batches.
__global__ void final_kernel(float* __restrict__ out) {
    const int b = threadIdx.x;  // 512 threads
    float v = g_total[b] - g_real[b];
    __shared__ float rr[16];
    #pragma unroll
    for (int o = 16; o > 0; o >>= 1) v += __shfl_xor_sync(0xffffffffu, v, o);
    if ((b & 31) == 0) rr[b >> 5] = v;
    __syncthreads();
    if (b < 16) {
        float x = rr[b];
        #pragma unroll
        for (int o = 8; o > 0; o >>= 1) x += __shfl_xor_sync(0x0000ffffu, x, o);
        if (b == 0) out[0] = x;
    }
}

extern "C" void kernel_launch(void* const* d_in, const int* in_sizes, int n_in,
                              void* d_out, int out_size) {
    const float* emis   = (const float*)d_in[0];
    const int*   labels = (const int*)d_in[1];
    const float* trans  = (const float*)d_in[2];
    float*       out    = (float*)d_out;

    const size_t smem = (NS * STRIDE + 512 + 32 + 16) * sizeof(float);
    cudaFuncSetAttribute(main_kernel, cudaFuncAttributeMaxDynamicSharedMemorySize, (int)smem);

    prep_kernel<<<(NS * NS + 255) / 256, 256>>>(trans);
    main_kernel<<<BB / 4, NTHR, smem>>>(emis);
    real_kernel<<<BB, 128>>>(emis, labels, trans);
    final_kernel<<<1, BB>>>(out);
}

// round 6
// speedup vs baseline: 2.5308x; 1.1324x over previous
#include <cuda_runtime.h>
#include <cstdint>
#include <cstddef>

#define BB 512
#define TT 512
#define LBL 126
#define NS 128            // L + 2
#define STRIDE 132        // padded row stride for conflict-free LDS.128
#define FILLF (-1000.0f)
#define LOG2E 1.4426950408889634f
#define LN2   0.6931471805599453f
#define NTHR 256          // 2 groups of 128; each thread = 1 column x 2 batches

__device__ float g_V[NS * NS];    // g_V[j*NS+i] = 2^(trans[i][j]*log2e); row L := 1.0 (U trick)
__device__ float g_total[BB];
__device__ float g_real[BB];

__device__ __forceinline__ float ex2f(float x) {
    float y; asm("ex2.approx.ftz.f32 %0, %1;" : "=f"(y) : "f"(x)); return y;
}
__device__ __forceinline__ float lg2f(float x) {
    float y; asm("lg2.approx.ftz.f32 %0, %1;" : "=f"(y) : "f"(x)); return y;
}

// Packed MAC: p = u2*v2 (f32x2), P2 += p (f32x2), m0/m1 = max with p's halves.
__device__ __forceinline__ void mac2(uint64_t u2, uint64_t v2,
                                     uint64_t& P2, float& m0, float& m1) {
    asm("{\n\t"
        ".reg .b64 p;\n\t"
        ".reg .f32 lo, hi;\n\t"
        "mul.rn.f32x2 p, %3, %4;\n\t"
        "mov.b64 {lo, hi}, p;\n\t"
        "add.rn.f32x2 %0, %0, p;\n\t"
        "max.f32 %1, %1, lo;\n\t"
        "max.f32 %2, %2, hi;\n\t"
        "}"
        : "+l"(P2), "+f"(m0), "+f"(m1)
        : "l"(u2), "l"(v2));
}

__device__ __forceinline__ float2 u64f2(uint64_t x) {
    float2 r; asm("mov.b64 {%0,%1}, %2;" : "=f"(r.x), "=f"(r.y) : "l"(x)); return r;
}

// Precompute V (transposed, exponentiated, log2 domain). Row LBL of V^T is set
// to 1.0 so that thread LBL's inner-loop sum computes U = sum_i u_i for free
// (true column-L transitions are all FILL -> V=0; value overridden in-kernel).
__global__ void prep_kernel(const float* __restrict__ trans) {
    int o = blockIdx.x * blockDim.x + threadIdx.x;   // o = j*NS + i
    if (o < NS * NS) {
        int j = o >> 7, i = o & 127;
        g_V[o] = (j == LBL) ? 1.0f : ex2f(trans[i * NS + j] * LOG2E);
    }
}

// Main forward scan. 128 CTAs x 256 threads; group g (128 thr) handles
// batches (bid*4 + 2g, bid*4 + 2g + 1); thread j owns column j of both.
// State per batch: u_j = 2^(e_j) in smem (double-buffered), scalar acc A,
// normalizer C (lagged d-max) and delta = max e. pre_j = A + e_j (log2 dom.).
__global__ void __launch_bounds__(NTHR, 1) main_kernel(const float* __restrict__ emis) {
    extern __shared__ float sm[];
    const int tid  = threadIdx.x;
    const int g    = tid >> 7;
    const int j    = tid & 127;
    const int w    = (tid >> 5) & 3;
    const int lane = tid & 31;

    float*  VT   = sm;                                  // NS*STRIDE
    float*  ubuf = sm + NS * STRIDE + g * 512;          // 2 bufs x (uA[128],uB[128])
    float4* red  = reinterpret_cast<float4*>(sm + NS * STRIDE + 1024) + g * 8;  // 2 bufs x 4

    for (int k = tid; k < NS * NS; k += NTHR)
        VT[(k >> 7) * STRIDE + (k & 127)] = g_V[k];

    const int bA = blockIdx.x * 4 + g * 2;
    const int bB = bA + 1;
    const float CF = FILLF * LOG2E;
    const int barid = g + 1;

    // init u (buffer 0): indicator of start state L
    ubuf[j]       = (j == LBL) ? 1.0f : 0.0f;   // uA
    ubuf[128 + j] = (j == LBL) ? 1.0f : 0.0f;   // uB

    float accA = 0.0f, accB = 0.0f;
    float CnA = 0.0f, CnB = 0.0f;       // lagged normalizers
    float dltA = 0.0f, dltB = 0.0f;     // delta = max e of current u

    const float* eA = emis + (size_t)bA * TT * LBL;
    const float* eB = emis + (size_t)bB * TT * LBL;
    float rawA = 0.0f, rawB = 0.0f;
    if (j < LBL) { rawA = eA[j]; rawB = eB[j]; }
    asm volatile("bar.sync %0, 128;" :: "r"(barid) : "memory");

    const float* vrow = VT + j * STRIDE;
    const float* ucur = ubuf;           // reads buf[t&1]
    float*       unxt = ubuf + 256;     // writes buf[(t+1)&1]

    for (int t = 0; t <= TT; ++t) {
        float obsA, obsB;
        if (t < TT) {
            obsA = (j < LBL) ? rawA * LOG2E : CF;
            obsB = (j < LBL) ? rawB * LOG2E : CF;
        } else {
            obsA = (j == LBL + 1) ? 0.0f : CF;
            obsB = obsA;
        }
        if (t + 1 < TT && j < LBL) {          // prefetch next emission row
            rawA = eA[(size_t)(t + 1) * LBL + j];
            rawB = eB[(size_t)(t + 1) * LBL + j];
        }

        // Inner matvec+max: p = u_i * V_ij ; mp = max p ; Ps = sum p.
        const float* uA = ucur;
        const float* uB = ucur + 128;
        uint64_t PA0 = 0, PA1 = 0, PB0 = 0, PB1 = 0;
        float mA0 = 0.f, mA1 = 0.f, mA2 = 0.f, mA3 = 0.f;
        float mB0 = 0.f, mB1 = 0.f, mB2 = 0.f, mB3 = 0.f;
        #pragma unroll 8
        for (int i = 0; i < NS; i += 4) {
            ulonglong2 v2 = *reinterpret_cast<const ulonglong2*>(vrow + i);
            ulonglong2 a2 = *reinterpret_cast<const ulonglong2*>(uA + i);  // broadcast
            ulonglong2 b2 = *reinterpret_cast<const ulonglong2*>(uB + i);  // broadcast
            mac2(a2.x, v2.x, PA0, mA0, mA1);
            mac2(a2.y, v2.y, PA1, mA2, mA3);
            mac2(b2.x, v2.x, PB0, mB0, mB1);
            mac2(b2.y, v2.y, PB1, mB2, mB3);
        }
        float2 fA0 = u64f2(PA0), fA1 = u64f2(PA1);
        float2 fB0 = u64f2(PB0), fB1 = u64f2(PB1);
        const float PsA = (fA0.x + fA0.y) + (fA1.x + fA1.y);
        const float PsB = (fB0.x + fB0.y) + (fB1.x + fB1.y);
        const float mpA = fmaxf(fmaxf(mA0, mA1), fmaxf(mA2, mA3));
        const float mpB = fmaxf(fmaxf(mB0, mB1), fmaxf(mB2, mB3));

        // Column L: Ps_L = U (V-row trick); s_L = U*2^-delta, lm_L = CF + delta.
        const bool isL = (j == LBL);
        const float lmA = isL ? (CF + dltA) : lg2f(mpA);
        const float lmB = isL ? (CF + dltB) : lg2f(mpB);
        const float sA  = PsA * ex2f(isL ? -dltA : -lmA);
        const float sB  = PsB * ex2f(isL ? -dltB : -lmB);
        const float dA  = obsA + lmA;   // pre_new_j = A + lg2S + d_j
        const float dB  = obsB + lmB;

        // Next u with LAGGED normalizer (off the reduction critical path).
        unxt[j]       = ex2f(dA - CnA);
        unxt[128 + j] = ex2f(dB - CnB);

        // Reduce (sum s, max d) over the 128-thread group. Fixed order.
        float rsA = sA, rsB = sB, rdA = dA, rdB = dB;
        #pragma unroll
        for (int o = 16; o > 0; o >>= 1) {
            rsA += __shfl_xor_sync(0xffffffffu, rsA, o);
            rsB += __shfl_xor_sync(0xffffffffu, rsB, o);
            rdA = fmaxf(rdA, __shfl_xor_sync(0xffffffffu, rdA, o));
            rdB = fmaxf(rdB, __shfl_xor_sync(0xffffffffu, rdB, o));
        }
        float4* rbuf = red + (t & 1) * 4;
        if (lane == 0) rbuf[w] = make_float4(rsA, rsB, rdA, rdB);
        asm volatile("bar.sync %0, 128;" :: "r"(barid) : "memory");
        const float4 q0 = rbuf[0], q1 = rbuf[1], q2 = rbuf[2], q3 = rbuf[3];
        const float SA  = (q0.x + q1.x) + (q2.x + q3.x);
        const float SB  = (q0.y + q1.y) + (q2.y + q3.y);
        const float dmA = fmaxf(fmaxf(q0.z, q1.z), fmaxf(q2.z, q3.z));
        const float dmB = fmaxf(fmaxf(q0.w, q1.w), fmaxf(q2.w, q3.w));

        accA += lg2f(SA) + CnA;
        accB += lg2f(SB) + CnB;
        dltA = dmA - CnA;  CnA = dmA;
        dltB = dmB - CnB;  CnB = dmB;

        const float* tmp = ucur; ucur = unxt; unxt = const_cast<float*>(tmp);
    }

    // Final per-batch logsumexp: total = A + lg2(sum_j u_j)  (e bounded by delta).
    float ruA = ucur[j], ruB = ucur[128 + j];
    #pragma unroll
    for (int o = 16; o > 0; o >>= 1) {
        ruA += __shfl_xor_sync(0xffffffffu, ruA, o);
        ruB += __shfl_xor_sync(0xffffffffu, ruB, o);
    }
    if (lane == 0) red[w] = make_float4(ruA, ruB, 0.f, 0.f);
    asm volatile("bar.sync %0, 128;" :: "r"(barid) : "memory");
    if (j == 0) {
        const float4 q0 = red[0], q1 = red[1], q2 = red[2], q3 = red[3];
        const float UA = (q0.x + q1.x) + (q2.x + q3.x);
        const float UB = (q0.y + q1.y) + (q2.y + q3.y);
        g_total[bA] = (accA + lg2f(UA)) * LN2;
        g_total[bB] = (accB + lg2f(UB)) * LN2;
    }
}

// Real path score per batch: emission gather + transition chain.
__global__ void real_kernel(const float* __restrict__ emis,
                            const int* __restrict__ labels,
                            const float* __restrict__ trans) {
    const int b = blockIdx.x;
    const int tid = threadIdx.x;  // 128 threads
    const int*   lab = labels + (size_t)b * TT;
    const float* eb  = emis + (size_t)b * TT * LBL;

    float acc = 0.f;
    for (int t = tid; t < TT; t += 128) {
        const int l = lab[t];
        acc += eb[(size_t)t * LBL + l];
        const int prev = (t == 0) ? LBL : lab[t - 1];
        acc += trans[prev * NS + l];
    }
    if (tid == 0) acc += trans[lab[TT - 1] * NS + (LBL + 1)];  // last -> END

    __shared__ float rr[4];
    #pragma unroll
    for (int o = 16; o > 0; o >>= 1) acc += __shfl_xor_sync(0xffffffffu, acc, o);
    if ((tid & 31) == 0) rr[tid >> 5] = acc;
    __syncthreads();
    if (tid == 0) g_real[b] = (rr[0] + rr[1]) + (rr[2] + rr[3]);
}

// Deterministic final sum over batches.
__global__ void final_kernel(float* __restrict__ out) {
    const int b = threadIdx.x;  // 512 threads
    float v = g_total[b] - g_real[b];
    __shared__ float rr[16];
    #pragma unroll
    for (int o = 16; o > 0; o >>= 1) v += __shfl_xor_sync(0xffffffffu, v, o);
    if ((b & 31) == 0) rr[b >> 5] = v;
    __syncthreads();
    if (b < 16) {
        float x = rr[b];
        #pragma unroll
        for (int o = 8; o > 0; o >>= 1) x += __shfl_xor_sync(0x0000ffffu, x, o);
        if (b == 0) out[0] = x;
    }
}

extern "C" void kernel_launch(void* const* d_in, const int* in_sizes, int n_in,
                              void* d_out, int out_size) {
    const float* emis   = (const float*)d_in[0];
    const int*   labels = (const int*)d_in[1];
    const float* trans  = (const float*)d_in[2];
    float*       out    = (float*)d_out;

    // VT + 2 groups x (2 u-buffers of 256 floats) + 2 groups x 2 x 4 float4 red
    const size_t smem = (NS * STRIDE + 1024 + 64) * sizeof(float);
    cudaFuncSetAttribute(main_kernel, cudaFuncAttributeMaxDynamicSharedMemorySize, (int)smem);

    prep_kernel<<<(NS * NS + 255) / 256, 256>>>(trans);
    main_kernel<<<BB / 4, NTHR, smem>>>(emis);
    real_kernel<<<BB, 128>>>(emis, labels, trans);
    final_kernel<<<1, BB>>>(out);
}